// round 4
// baseline (speedup 1.0000x reference)
#include <cuda_runtime.h>

// ---------------------------------------------------------------------------
// Fused dopri5 neural-ODE integrator, fp32 SIMT baseline.
//   x:[4096,256], W1/W2:[256,256], 40 steps x 6 stages, f(x)=tanh(x@W1)@W2
// Each CTA owns RTILE=16 rows for the whole integration:
//   - x (and final accumulator) live in registers (4 x float4 / thread)
//   - k1..k5 in smem (k6 reuses k2's slot; k2 is dead for the final combo)
//   - stage input xs and tanh intermediate hb in smem (padded lda=260)
//   - W streamed global->smem via cp.async, double-buffered 32-row tiles
// ---------------------------------------------------------------------------

#define NSTEPS  40
#define HSTEP   0.025f
#define DIMD    256
#define RTILE   16
#define LDA     260          // padded row stride for xs/hb (floats)
#define KT      32           // k-dim tile rows per W smem tile
#define NT      (DIMD / KT)  // 8 tiles per GEMM
#define THREADS 256

#define WBUF_F (2 * KT * DIMD)        // 16384 floats (double-buffered W tile)
#define KS_F   (5 * RTILE * DIMD)     // 20480 floats (k slots)
#define XS_F   (RTILE * LDA)          // 4160 floats
#define SMEM_FLOATS (WBUF_F + KS_F + 2 * XS_F)
#define SMEM_BYTES  (SMEM_FLOATS * 4) // 180736 B

// ---------------- cp.async helpers ----------------
__device__ __forceinline__ void cp_async16(void* sdst, const void* gsrc) {
    unsigned s = (unsigned)__cvta_generic_to_shared(sdst);
    asm volatile("cp.async.cg.shared.global [%0], [%1], 16;\n" ::"r"(s), "l"(gsrc));
}
__device__ __forceinline__ void cp_commit() {
    asm volatile("cp.async.commit_group;\n");
}
__device__ __forceinline__ void cp_wait0() {
    asm volatile("cp.async.wait_group 0;\n");
}

// precise-enough tanh (~1e-7 rel): immune to -use_fast_math tanhf approx
__device__ __forceinline__ float fast_tanh(float x) {
    float ax = fabsf(x);
    float e  = __expf(2.0f * ax);          // inf for large ax -> t = 1 exactly
    float t  = 1.0f - 2.0f / (e + 1.0f);
    return copysignf(t, x);
}

__device__ __forceinline__ float4 f4fma(float c, float4 a, float4 b) {
    return make_float4(fmaf(c, a.x, b.x), fmaf(c, a.y, b.y),
                       fmaf(c, a.z, b.z), fmaf(c, a.w, b.w));
}

// ---------------------------------------------------------------------------
// C[16 x 256] = A[16 x 256 (lda=260, smem)] x W[256 x 256 (global, row-major)]
// Per-thread tile: 4 rows x 4 cols. Thread map:
//   row0 = (lane&3)*4            (4 row-groups -> W smem reads broadcast x4)
//   col0 = (warp*8 + lane>>2)*4  (64 col-groups)
// W tiles staged via cp.async double buffer; one __syncthreads per tile.
// ---------------------------------------------------------------------------
__device__ __forceinline__ void gemm16x256(const float* __restrict__ A,
                                           const float* __restrict__ Wg,
                                           float* __restrict__ wbuf,
                                           int row0, int col0, int t,
                                           float acc[4][4]) {
#pragma unroll
    for (int r = 0; r < 4; r++)
#pragma unroll
        for (int c = 0; c < 4; c++) acc[r][c] = 0.0f;

    // prefetch tile 0
#pragma unroll
    for (int i = 0; i < 8; i++) {
        int e4 = (t + i * THREADS) * 4;
        cp_async16(&wbuf[e4], Wg + e4);
    }
    cp_commit();

#pragma unroll 1
    for (int kt = 0; kt < NT; kt++) {
        cp_wait0();
        __syncthreads();   // tile kt visible; all threads done with tile kt-1
        if (kt + 1 < NT) { // prefetch next tile into the other buffer
            const float* src = Wg + (kt + 1) * KT * DIMD;
            float* dst = wbuf + ((kt + 1) & 1) * KT * DIMD;
#pragma unroll
            for (int i = 0; i < 8; i++) {
                int e4 = (t + i * THREADS) * 4;
                cp_async16(&dst[e4], src + e4);
            }
            cp_commit();
        }
        const float* wb = wbuf + (kt & 1) * KT * DIMD;
        const float* Ab = A + kt * KT;
#pragma unroll 4
        for (int kk = 0; kk < KT; kk += 4) {
            float av[4][4];
#pragma unroll
            for (int r = 0; r < 4; r++) {
                float4 a = *(const float4*)&Ab[(row0 + r) * LDA + kk];
                av[r][0] = a.x; av[r][1] = a.y; av[r][2] = a.z; av[r][3] = a.w;
            }
#pragma unroll
            for (int j = 0; j < 4; j++) {
                float4 wv = *(const float4*)&wb[(kk + j) * DIMD + col0];
#pragma unroll
                for (int r = 0; r < 4; r++) {
                    acc[r][0] = fmaf(av[r][j], wv.x, acc[r][0]);
                    acc[r][1] = fmaf(av[r][j], wv.y, acc[r][1]);
                    acc[r][2] = fmaf(av[r][j], wv.z, acc[r][2]);
                    acc[r][3] = fmaf(av[r][j], wv.w, acc[r][3]);
                }
            }
        }
    }
}

__global__ void __launch_bounds__(THREADS, 1)
ode_dopri5_kernel(const float* __restrict__ x0, const float* __restrict__ W1,
                  const float* __restrict__ W2, float* __restrict__ out) {
    extern __shared__ float smem[];
    float* wbuf = smem;               // [2][KT][256]
    float* ks   = smem + WBUF_F;      // [5][16][256]  (slot1 reused for k6)
    float* xs   = ks + KS_F;          // [16][260] stage input
    float* hb   = xs + XS_F;          // [16][260] tanh intermediate

    const int t    = threadIdx.x;
    const int lane = t & 31;
    const int wrp  = t >> 5;
    const int row0 = (lane & 3) * 4;
    const int col0 = (wrp * 8 + (lane >> 2)) * 4;
    const int gr0  = blockIdx.x * RTILE;

    // load x slab: registers (elementwise layout) + xs (stage-1 input)
    float4 xr[4];
#pragma unroll
    for (int i = 0; i < 4; i++) {
        int idx = t + i * THREADS;       // float4 index in [0,1024)
        int row = idx >> 6, c4 = idx & 63;
        float4 v = *(const float4*)&x0[(gr0 + row) * DIMD + c4 * 4];
        xr[i] = v;
        *(float4*)&xs[row * LDA + c4 * 4] = v;
    }
    // (first gemm's internal sync orders these xs writes before reads)

    const float h = HSTEP;
    const float A21 = 0.2f;
    const float A31 = (float)(3.0 / 40.0),      A32 = (float)(9.0 / 40.0);
    const float A41 = (float)(44.0 / 45.0),     A42 = (float)(-56.0 / 15.0);
    const float A43 = (float)(32.0 / 9.0);
    const float A51 = (float)(19372.0 / 6561.0), A52 = (float)(-25360.0 / 2187.0);
    const float A53 = (float)(64448.0 / 6561.0), A54 = (float)(-212.0 / 729.0);
    const float A61 = (float)(9017.0 / 3168.0),  A62 = (float)(-355.0 / 33.0);
    const float A63 = (float)(46732.0 / 5247.0), A64 = (float)(49.0 / 176.0);
    const float A65 = (float)(-5103.0 / 18656.0);
    const float B1 = (float)(35.0 / 384.0),   B3 = (float)(500.0 / 1113.0);
    const float B4 = (float)(125.0 / 192.0),  B5 = (float)(-2187.0 / 6784.0);
    const float B6 = (float)(11.0 / 84.0);

#pragma unroll 1
    for (int step = 0; step < NSTEPS; step++) {
#pragma unroll 1
        for (int s = 0; s < 6; s++) {
            float acc[4][4];

            // GEMM1 + tanh epilogue -> hb
            gemm16x256(xs, W1, wbuf, row0, col0, t, acc);
#pragma unroll
            for (int r = 0; r < 4; r++) {
                float4 v;
                v.x = fast_tanh(acc[r][0]);
                v.y = fast_tanh(acc[r][1]);
                v.z = fast_tanh(acc[r][2]);
                v.w = fast_tanh(acc[r][3]);
                *(float4*)&hb[(row0 + r) * LDA + col0] = v;
            }

            // GEMM2 -> k slot (k6 -> slot 1, k2's slot is dead by then)
            gemm16x256(hb, W2, wbuf, row0, col0, t, acc);
            const int slot = (s == 5) ? 1 : s;
            float* kd = ks + slot * (RTILE * DIMD);
#pragma unroll
            for (int r = 0; r < 4; r++) {
                float4 v = make_float4(acc[r][0], acc[r][1], acc[r][2], acc[r][3]);
                *(float4*)&kd[(row0 + r) * DIMD + col0] = v;
            }
            __syncthreads();  // k slot visible to all before elementwise reads

            // elementwise: build next stage input (or final x update)
#pragma unroll
            for (int i = 0; i < 4; i++) {
                int idx = t + i * THREADS;
                int row = idx >> 6, c4 = idx & 63;
                const float4* K0 = (const float4*)&ks[0 * RTILE * DIMD] + idx;
                const float4* K1 = (const float4*)&ks[1 * RTILE * DIMD] + idx;
                const float4* K2 = (const float4*)&ks[2 * RTILE * DIMD] + idx;
                const float4* K3 = (const float4*)&ks[3 * RTILE * DIMD] + idx;
                const float4* K4 = (const float4*)&ks[4 * RTILE * DIMD] + idx;
                float4 x = xr[i];
                float4 o;
                if (s == 0) {
                    o = f4fma(h * A21, *K0, x);
                } else if (s == 1) {
                    o = f4fma(h * A32, *K1, f4fma(h * A31, *K0, x));
                } else if (s == 2) {
                    o = f4fma(h * A43, *K2,
                        f4fma(h * A42, *K1, f4fma(h * A41, *K0, x)));
                } else if (s == 3) {
                    o = f4fma(h * A54, *K3, f4fma(h * A53, *K2,
                        f4fma(h * A52, *K1, f4fma(h * A51, *K0, x))));
                } else if (s == 4) {
                    o = f4fma(h * A65, *K4, f4fma(h * A64, *K3,
                        f4fma(h * A63, *K2, f4fma(h * A62, *K1,
                        f4fma(h * A61, *K0, x)))));
                } else {  // s == 5: final combo; K1 holds k6
                    o = f4fma(h * B6, *K1, f4fma(h * B5, *K4,
                        f4fma(h * B4, *K3, f4fma(h * B3, *K2,
                        f4fma(h * B1, *K0, x)))));
                    xr[i] = o;  // new x
                }
                *(float4*)&xs[row * LDA + c4 * 4] = o;  // stage input / next-step x
            }
            // next gemm's first internal sync orders xs writes before reads
        }
    }

    // final x -> out
#pragma unroll
    for (int i = 0; i < 4; i++) {
        int idx = t + i * THREADS;
        int row = idx >> 6, c4 = idx & 63;
        *(float4*)&out[(gr0 + row) * DIMD + c4 * 4] = xr[i];
    }
}

extern "C" void kernel_launch(void* const* d_in, const int* in_sizes, int n_in,
                              void* d_out, int out_size) {
    (void)in_sizes; (void)n_in; (void)out_size;
    const float* x0 = (const float*)d_in[0];
    const float* W1 = (const float*)d_in[1];
    const float* W2 = (const float*)d_in[2];
    float* out = (float*)d_out;

    cudaFuncSetAttribute(ode_dopri5_kernel,
                         cudaFuncAttributeMaxDynamicSharedMemorySize, SMEM_BYTES);
    ode_dopri5_kernel<<<4096 / RTILE, THREADS, SMEM_BYTES>>>(x0, W1, W2, out);
}

// round 5
// speedup vs baseline: 1.0026x; 1.0026x over previous
#include <cuda_runtime.h>

// ---------------------------------------------------------------------------
// Fused dopri5 neural-ODE integrator, fp32 SIMT baseline.
//   x:[4096,256], W1/W2:[256,256], 40 steps x 6 stages, f(x)=tanh(x@W1)@W2
// Each CTA owns RTILE=16 rows for the whole integration:
//   - x (and final accumulator) live in registers (4 x float4 / thread)
//   - k1..k5 in smem (k6 reuses k2's slot; k2 is dead for the final combo)
//   - stage input xs and tanh intermediate hb in smem (padded lda=260)
//   - W streamed global->smem via cp.async, double-buffered 32-row tiles
// ---------------------------------------------------------------------------

#define NSTEPS  40
#define HSTEP   0.025f
#define DIMD    256
#define RTILE   16
#define LDA     260          // padded row stride for xs/hb (floats)
#define KT      32           // k-dim tile rows per W smem tile
#define NT      (DIMD / KT)  // 8 tiles per GEMM
#define THREADS 256

#define WBUF_F (2 * KT * DIMD)        // 16384 floats (double-buffered W tile)
#define KS_F   (5 * RTILE * DIMD)     // 20480 floats (k slots)
#define XS_F   (RTILE * LDA)          // 4160 floats
#define SMEM_FLOATS (WBUF_F + KS_F + 2 * XS_F)
#define SMEM_BYTES  (SMEM_FLOATS * 4) // 180736 B

// ---------------- cp.async helpers ----------------
__device__ __forceinline__ void cp_async16(void* sdst, const void* gsrc) {
    unsigned s = (unsigned)__cvta_generic_to_shared(sdst);
    asm volatile("cp.async.cg.shared.global [%0], [%1], 16;\n" ::"r"(s), "l"(gsrc));
}
__device__ __forceinline__ void cp_commit() {
    asm volatile("cp.async.commit_group;\n");
}
__device__ __forceinline__ void cp_wait0() {
    asm volatile("cp.async.wait_group 0;\n");
}

// precise-enough tanh (~1e-7 rel): immune to -use_fast_math tanhf approx
__device__ __forceinline__ float fast_tanh(float x) {
    float ax = fabsf(x);
    float e  = __expf(2.0f * ax);          // inf for large ax -> t = 1 exactly
    float t  = 1.0f - 2.0f / (e + 1.0f);
    return copysignf(t, x);
}

__device__ __forceinline__ float4 f4fma(float c, float4 a, float4 b) {
    return make_float4(fmaf(c, a.x, b.x), fmaf(c, a.y, b.y),
                       fmaf(c, a.z, b.z), fmaf(c, a.w, b.w));
}

// ---------------------------------------------------------------------------
// C[16 x 256] = A[16 x 256 (lda=260, smem)] x W[256 x 256 (global, row-major)]
// Per-thread tile: 4 rows x 4 cols. Thread map:
//   row0 = (lane&3)*4            (4 row-groups -> W smem reads broadcast x4)
//   col0 = (warp*8 + lane>>2)*4  (64 col-groups)
// W tiles staged via cp.async double buffer; one __syncthreads per tile.
// ---------------------------------------------------------------------------
__device__ __forceinline__ void gemm16x256(const float* __restrict__ A,
                                           const float* __restrict__ Wg,
                                           float* __restrict__ wbuf,
                                           int row0, int col0, int t,
                                           float acc[4][4]) {
#pragma unroll
    for (int r = 0; r < 4; r++)
#pragma unroll
        for (int c = 0; c < 4; c++) acc[r][c] = 0.0f;

    // prefetch tile 0
#pragma unroll
    for (int i = 0; i < 8; i++) {
        int e4 = (t + i * THREADS) * 4;
        cp_async16(&wbuf[e4], Wg + e4);
    }
    cp_commit();

#pragma unroll 1
    for (int kt = 0; kt < NT; kt++) {
        cp_wait0();
        __syncthreads();   // tile kt visible; all threads done with tile kt-1
        if (kt + 1 < NT) { // prefetch next tile into the other buffer
            const float* src = Wg + (kt + 1) * KT * DIMD;
            float* dst = wbuf + ((kt + 1) & 1) * KT * DIMD;
#pragma unroll
            for (int i = 0; i < 8; i++) {
                int e4 = (t + i * THREADS) * 4;
                cp_async16(&dst[e4], src + e4);
            }
            cp_commit();
        }
        const float* wb = wbuf + (kt & 1) * KT * DIMD;
        const float* Ab = A + kt * KT;
#pragma unroll 4
        for (int kk = 0; kk < KT; kk += 4) {
            float av[4][4];
#pragma unroll
            for (int r = 0; r < 4; r++) {
                float4 a = *(const float4*)&Ab[(row0 + r) * LDA + kk];
                av[r][0] = a.x; av[r][1] = a.y; av[r][2] = a.z; av[r][3] = a.w;
            }
#pragma unroll
            for (int j = 0; j < 4; j++) {
                float4 wv = *(const float4*)&wb[(kk + j) * DIMD + col0];
#pragma unroll
                for (int r = 0; r < 4; r++) {
                    acc[r][0] = fmaf(av[r][j], wv.x, acc[r][0]);
                    acc[r][1] = fmaf(av[r][j], wv.y, acc[r][1]);
                    acc[r][2] = fmaf(av[r][j], wv.z, acc[r][2]);
                    acc[r][3] = fmaf(av[r][j], wv.w, acc[r][3]);
                }
            }
        }
    }
}

__global__ void __launch_bounds__(THREADS, 1)
ode_dopri5_kernel(const float* __restrict__ x0, const float* __restrict__ W1,
                  const float* __restrict__ W2, float* __restrict__ out) {
    extern __shared__ float smem[];
    float* wbuf = smem;               // [2][KT][256]
    float* ks   = smem + WBUF_F;      // [5][16][256]  (slot1 reused for k6)
    float* xs   = ks + KS_F;          // [16][260] stage input
    float* hb   = xs + XS_F;          // [16][260] tanh intermediate

    const int t    = threadIdx.x;
    const int lane = t & 31;
    const int wrp  = t >> 5;
    const int row0 = (lane & 3) * 4;
    const int col0 = (wrp * 8 + (lane >> 2)) * 4;
    const int gr0  = blockIdx.x * RTILE;

    // load x slab: registers (elementwise layout) + xs (stage-1 input)
    float4 xr[4];
#pragma unroll
    for (int i = 0; i < 4; i++) {
        int idx = t + i * THREADS;       // float4 index in [0,1024)
        int row = idx >> 6, c4 = idx & 63;
        float4 v = *(const float4*)&x0[(gr0 + row) * DIMD + c4 * 4];
        xr[i] = v;
        *(float4*)&xs[row * LDA + c4 * 4] = v;
    }
    // (first gemm's internal sync orders these xs writes before reads)

    const float h = HSTEP;
    const float A21 = 0.2f;
    const float A31 = (float)(3.0 / 40.0),      A32 = (float)(9.0 / 40.0);
    const float A41 = (float)(44.0 / 45.0),     A42 = (float)(-56.0 / 15.0);
    const float A43 = (float)(32.0 / 9.0);
    const float A51 = (float)(19372.0 / 6561.0), A52 = (float)(-25360.0 / 2187.0);
    const float A53 = (float)(64448.0 / 6561.0), A54 = (float)(-212.0 / 729.0);
    const float A61 = (float)(9017.0 / 3168.0),  A62 = (float)(-355.0 / 33.0);
    const float A63 = (float)(46732.0 / 5247.0), A64 = (float)(49.0 / 176.0);
    const float A65 = (float)(-5103.0 / 18656.0);
    const float B1 = (float)(35.0 / 384.0),   B3 = (float)(500.0 / 1113.0);
    const float B4 = (float)(125.0 / 192.0),  B5 = (float)(-2187.0 / 6784.0);
    const float B6 = (float)(11.0 / 84.0);

#pragma unroll 1
    for (int step = 0; step < NSTEPS; step++) {
#pragma unroll 1
        for (int s = 0; s < 6; s++) {
            float acc[4][4];

            // GEMM1 + tanh epilogue -> hb
            gemm16x256(xs, W1, wbuf, row0, col0, t, acc);
#pragma unroll
            for (int r = 0; r < 4; r++) {
                float4 v;
                v.x = fast_tanh(acc[r][0]);
                v.y = fast_tanh(acc[r][1]);
                v.z = fast_tanh(acc[r][2]);
                v.w = fast_tanh(acc[r][3]);
                *(float4*)&hb[(row0 + r) * LDA + col0] = v;
            }

            // GEMM2 -> k slot (k6 -> slot 1, k2's slot is dead by then)
            gemm16x256(hb, W2, wbuf, row0, col0, t, acc);
            const int slot = (s == 5) ? 1 : s;
            float* kd = ks + slot * (RTILE * DIMD);
#pragma unroll
            for (int r = 0; r < 4; r++) {
                float4 v = make_float4(acc[r][0], acc[r][1], acc[r][2], acc[r][3]);
                *(float4*)&kd[(row0 + r) * DIMD + col0] = v;
            }
            __syncthreads();  // k slot visible to all before elementwise reads

            // elementwise: build next stage input (or final x update)
#pragma unroll
            for (int i = 0; i < 4; i++) {
                int idx = t + i * THREADS;
                int row = idx >> 6, c4 = idx & 63;
                const float4* K0 = (const float4*)&ks[0 * RTILE * DIMD] + idx;
                const float4* K1 = (const float4*)&ks[1 * RTILE * DIMD] + idx;
                const float4* K2 = (const float4*)&ks[2 * RTILE * DIMD] + idx;
                const float4* K3 = (const float4*)&ks[3 * RTILE * DIMD] + idx;
                const float4* K4 = (const float4*)&ks[4 * RTILE * DIMD] + idx;
                float4 x = xr[i];
                float4 o;
                if (s == 0) {
                    o = f4fma(h * A21, *K0, x);
                } else if (s == 1) {
                    o = f4fma(h * A32, *K1, f4fma(h * A31, *K0, x));
                } else if (s == 2) {
                    o = f4fma(h * A43, *K2,
                        f4fma(h * A42, *K1, f4fma(h * A41, *K0, x)));
                } else if (s == 3) {
                    o = f4fma(h * A54, *K3, f4fma(h * A53, *K2,
                        f4fma(h * A52, *K1, f4fma(h * A51, *K0, x))));
                } else if (s == 4) {
                    o = f4fma(h * A65, *K4, f4fma(h * A64, *K3,
                        f4fma(h * A63, *K2, f4fma(h * A62, *K1,
                        f4fma(h * A61, *K0, x)))));
                } else {  // s == 5: final combo; K1 holds k6
                    o = f4fma(h * B6, *K1, f4fma(h * B5, *K4,
                        f4fma(h * B4, *K3, f4fma(h * B3, *K2,
                        f4fma(h * B1, *K0, x)))));
                    xr[i] = o;  // new x
                }
                *(float4*)&xs[row * LDA + c4 * 4] = o;  // stage input / next-step x
            }
            // next gemm's first internal sync orders xs writes before reads
        }
    }

    // final x -> out
#pragma unroll
    for (int i = 0; i < 4; i++) {
        int idx = t + i * THREADS;
        int row = idx >> 6, c4 = idx & 63;
        *(float4*)&out[(gr0 + row) * DIMD + c4 * 4] = xr[i];
    }
}

extern "C" void kernel_launch(void* const* d_in, const int* in_sizes, int n_in,
                              void* d_out, int out_size) {
    (void)in_sizes; (void)n_in; (void)out_size;
    const float* x0 = (const float*)d_in[0];
    const float* W1 = (const float*)d_in[1];
    const float* W2 = (const float*)d_in[2];
    float* out = (float*)d_out;

    cudaFuncSetAttribute(ode_dopri5_kernel,
                         cudaFuncAttributeMaxDynamicSharedMemorySize, SMEM_BYTES);
    ode_dopri5_kernel<<<4096 / RTILE, THREADS, SMEM_BYTES>>>(x0, W1, W2, out);
}

// round 8
// speedup vs baseline: 2.5260x; 2.5195x over previous
#include <cuda_runtime.h>
#include <cuda_bf16.h>
#include <cstdint>

// ============================================================================
// Fused dopri5 neural-ODE via mma.sync bf16 (HMMA path valid on target sm_103).
// fp32 = bf16 hi/lo split, 3 products. Grid=128 CTAs x 32 rows, 8 warps.
// Acc fragments in registers; epilogues operate directly on fragments.
// W pre-transposed/split to [n][k] bf16 images; streamed in 64-k tiles.
// k1..k5 and x in L2-resident __device__ scratch, fragment layout.
// R7 fixes: load_chunk now loads the FULL 64KB tile (was 32KB -> garbage for
// k>=32 of each tile); added __syncthreads() between last ldmatrix of A and
// the epilogue's writes to A (WAR race across warps).
// ============================================================================

#define THREADS   256
#define NSTEPS    40
#define DIM       256
#define BROWS     4096
#define M_CTA     32
#define NCTA      (BROWS / M_CTA)        // 128
#define NGEMM     (NSTEPS * 6 * 2)       // 480
#define NCHUNK    (NGEMM * 4)            // 1920

#define LDA       264                    // A row stride (elements)
#define A_HI_OFF  0
#define A_LO_OFF  (M_CTA * LDA * 2)      // 16896
#define SMEM_W    (2 * M_CTA * LDA * 2)  // 33792
#define WROW_B    144                    // padded W row bytes (72 elems)
#define WHALF_B   (256 * WROW_B)         // 36864
#define WBUF_B    (2 * WHALF_B)          // 73728 (hi+lo)
#define SMEM_BYTES (SMEM_W + 2 * WBUF_B) // 181248

#define FRAG_CTA  (M_CTA * DIM)          // 8192 floats per CTA

__device__ __nv_bfloat16 g_wimg[2 * 2 * 256 * 256]; // [wi][half][n][k]
__device__ float g_k[5][BROWS * DIM];               // fragment layout
__device__ float g_x[BROWS * DIM];                  // fragment layout

__constant__ float c_cur[6] = {
    (float)(0.025 * 0.2), (float)(0.025 * 9.0 / 40.0), (float)(0.025 * 32.0 / 9.0),
    (float)(0.025 * -212.0 / 729.0), (float)(0.025 * -5103.0 / 18656.0),
    (float)(0.025 * 11.0 / 84.0)};
__constant__ float c_slot[6][5] = {
    {0.f, 0.f, 0.f, 0.f, 0.f},
    {(float)(0.025 * 3.0 / 40.0), 0.f, 0.f, 0.f, 0.f},
    {(float)(0.025 * 44.0 / 45.0), (float)(0.025 * -56.0 / 15.0), 0.f, 0.f, 0.f},
    {(float)(0.025 * 19372.0 / 6561.0), (float)(0.025 * -25360.0 / 2187.0),
     (float)(0.025 * 64448.0 / 6561.0), 0.f, 0.f},
    {(float)(0.025 * 9017.0 / 3168.0), (float)(0.025 * -355.0 / 33.0),
     (float)(0.025 * 46732.0 / 5247.0), (float)(0.025 * 49.0 / 176.0), 0.f},
    {(float)(0.025 * 35.0 / 384.0), 0.f, (float)(0.025 * 500.0 / 1113.0),
     (float)(0.025 * 125.0 / 192.0), (float)(0.025 * -2187.0 / 6784.0)}};

__device__ __forceinline__ uint32_t smem_u32(const void* p) {
    uint32_t a;
    asm("{ .reg .u64 t; cvta.to.shared.u64 t, %1; cvt.u32.u64 %0, t; }" : "=r"(a) : "l"(p));
    return a;
}
__device__ __forceinline__ void cp_async16(void* sdst, const void* gsrc) {
    unsigned s = (unsigned)__cvta_generic_to_shared(sdst);
    asm volatile("cp.async.cg.shared.global [%0], [%1], 16;\n" ::"r"(s), "l"(gsrc));
}
__device__ __forceinline__ void cp_commit() { asm volatile("cp.async.commit_group;\n" ::: "memory"); }
__device__ __forceinline__ void cp_wait0()  { asm volatile("cp.async.wait_group 0;\n" ::: "memory"); }

__device__ __forceinline__ void ldsm_x4(uint32_t* r, uint32_t addr) {
    asm volatile("ldmatrix.sync.aligned.m8n8.x4.shared.b16 {%0,%1,%2,%3}, [%4];"
                 : "=r"(r[0]), "=r"(r[1]), "=r"(r[2]), "=r"(r[3]) : "r"(addr));
}
__device__ __forceinline__ void mma_bf16(float* c, const uint32_t* a, const uint32_t* b) {
    asm volatile("mma.sync.aligned.m16n8k16.row.col.f32.bf16.bf16.f32 "
                 "{%0,%1,%2,%3}, {%4,%5,%6,%7}, {%8,%9}, {%0,%1,%2,%3};"
                 : "+f"(c[0]), "+f"(c[1]), "+f"(c[2]), "+f"(c[3])
                 : "r"(a[0]), "r"(a[1]), "r"(a[2]), "r"(a[3]), "r"(b[0]), "r"(b[1]));
}

__device__ __forceinline__ float tanh_f(float x) {
    float ax = fabsf(x);
    float e  = __expf(2.0f * ax);
    float t  = 1.0f - 2.0f / (e + 1.0f);
    return copysignf(t, x);
}
__device__ __forceinline__ uint32_t bpack(float a, float b) {
    __nv_bfloat162 h = __floats2bfloat162_rn(a, b);
    return *(uint32_t*)&h;
}
// write pair (col, col+1) of row into A_hi / A_lo smem
__device__ __forceinline__ void writeA(char* smem, int row, int col, float a, float b) {
    float ah = __bfloat162float(__float2bfloat16(a));
    float bh = __bfloat162float(__float2bfloat16(b));
    int off = (row * LDA + col) * 2;
    *(uint32_t*)(smem + A_HI_OFF + off) = bpack(ah, bh);
    *(uint32_t*)(smem + A_LO_OFF + off) = bpack(a - ah, b - bh);
}

// W^T, hi/lo split: g_wimg[wi][half][n][k] = half? lo : hi of W[k][n]
__global__ void prep_kernel(const float* __restrict__ W1, const float* __restrict__ W2) {
    int e = blockIdx.x * blockDim.x + threadIdx.x;   // k*256 + n
    int k = e >> 8, n = e & 255;
#pragma unroll
    for (int wi = 0; wi < 2; wi++) {
        float v = (wi ? W2 : W1)[k * 256 + n];
        __nv_bfloat16 hi = __float2bfloat16(v);
        float lo = v - __bfloat162float(hi);
        g_wimg[((wi * 2 + 0) << 16) + n * 256 + k] = hi;
        g_wimg[((wi * 2 + 1) << 16) + n * 256 + k] = __float2bfloat16(lo);
    }
}

// stream one 64-k tile (hi+lo, 64KB) of W[(ci/4)&1] into buffer ci&1
__device__ __forceinline__ void load_chunk(char* smem, int ci, int tid) {
    const int wi = (ci >> 2) & 1, kt = ci & 3;
    char* dst0 = smem + SMEM_W + (ci & 1) * WBUF_B;
#pragma unroll
    for (int i = 0; i < 16; i++) {
        int idx = tid + (i << 8);                 // 0..4095 x 16B = 64KB
        int half = idx >> 11, rem = idx & 2047;
        int r = rem >> 3, c = rem & 7;            // row 0..255, 8 x 16B per row
        const __nv_bfloat16* src = g_wimg +
            (((wi * 2 + half) << 16) + r * 256 + kt * 64 + c * 8);
        cp_async16(dst0 + half * WHALF_B + r * WROW_B + c * 16, src);
    }
    cp_commit();
}

__global__ void __launch_bounds__(THREADS, 1)
ode_hmma_kernel(const float* __restrict__ x0, float* __restrict__ out) {
    extern __shared__ __align__(16) char smem[];
    const uint32_t sb = smem_u32(smem);
    const int tid = threadIdx.x, warp = tid >> 5, lane = tid & 31;
    const int quad = lane >> 3, lrow = lane & 7;

    // ldmatrix per-thread address components
    const int a_row  = lrow + ((quad & 1) << 3);     // row within m16
    const int a_col8 = (quad >> 1) << 3;             // +8 k for matrices 2,3
    const int b_row  = lrow + ((quad >> 1) << 3);    // n row within n16
    const int b_kadd = (quad & 1) << 3;              // +8 k for matrices 1,3

    // epilogue / fragment coordinates
    const int erow = lane >> 2;                      // 0..7
    const int ecol = warp * 32 + 2 * (lane & 3);     // + ni*8
    const int fbase = blockIdx.x * FRAG_CTA + warp * 1024 + lane * 4;
    const int growb = blockIdx.x * M_CTA;

    // ---- init: x0 -> fragments (g_x) and A smem ----
#pragma unroll
    for (int mi = 0; mi < 2; mi++)
#pragma unroll
        for (int ni = 0; ni < 4; ni++) {
            int row = mi * 16 + erow, col = ecol + ni * 8;
            float2 v01 = *(const float2*)&x0[(growb + row) * DIM + col];
            float2 v23 = *(const float2*)&x0[(growb + row + 8) * DIM + col];
            *(float4*)&g_x[fbase + (mi * 4 + ni) * 128] =
                make_float4(v01.x, v01.y, v23.x, v23.y);
            writeA(smem, row, col, v01.x, v01.y);
            writeA(smem, row + 8, col, v23.x, v23.y);
        }

    load_chunk(smem, 0, tid);

    float acc[2][4][4];
    int ci = 0;
#pragma unroll 1
    for (int g = 0; g < NGEMM; g++) {
        const int s = (g >> 1) % 6, j = g & 1;
#pragma unroll
        for (int mi = 0; mi < 2; mi++)
#pragma unroll
            for (int ni = 0; ni < 4; ni++)
#pragma unroll
                for (int c = 0; c < 4; c++) acc[mi][ni][c] = 0.0f;

#pragma unroll 1
        for (int kt = 0; kt < 4; kt++, ci++) {
            cp_wait0();           // chunk ci resident (only it outstanding)
            __syncthreads();      // + all threads done with buf (ci-1)&1, A writes visible
            if (ci + 1 < NCHUNK) load_chunk(smem, ci + 1, tid);

            const uint32_t wb = sb + SMEM_W + (uint32_t)(ci & 1) * WBUF_B;
            const int kbase = kt * 64;
#pragma unroll
            for (int kq = 0; kq < 4; kq++) {
                const int kg = kbase + kq * 16;
                uint32_t ahi[2][4], alo[2][4], bhi[8], blo[8];
#pragma unroll
                for (int mi = 0; mi < 2; mi++) {
                    uint32_t ao = (uint32_t)(((mi * 16 + a_row) * LDA + kg + a_col8) * 2);
                    ldsm_x4(ahi[mi], sb + A_HI_OFF + ao);
                    ldsm_x4(alo[mi], sb + A_LO_OFF + ao);
                }
#pragma unroll
                for (int np = 0; np < 2; np++) {
                    uint32_t bo = (uint32_t)((warp * 32 + np * 16 + b_row) * WROW_B +
                                             (kq * 16 + b_kadd) * 2);
                    ldsm_x4(&bhi[np * 4], wb + bo);
                    ldsm_x4(&blo[np * 4], wb + WHALF_B + bo);
                }
#pragma unroll
                for (int mi = 0; mi < 2; mi++)
#pragma unroll
                    for (int ni = 0; ni < 4; ni++) {
                        mma_bf16(acc[mi][ni], ahi[mi], &bhi[ni * 2]);  // hi*hi
                        mma_bf16(acc[mi][ni], alo[mi], &bhi[ni * 2]);  // lo*hi
                        mma_bf16(acc[mi][ni], ahi[mi], &blo[ni * 2]);  // hi*lo
                    }
            }
        }

        // All warps finished ldmatrix reads of A before anyone rewrites it.
        __syncthreads();

        // ---- epilogue on fragments ----
        if (j == 0) {                      // h = tanh(x@W1) -> new A
#pragma unroll
            for (int mi = 0; mi < 2; mi++)
#pragma unroll
                for (int ni = 0; ni < 4; ni++) {
                    float* a = acc[mi][ni];
                    int row = mi * 16 + erow, col = ecol + ni * 8;
                    writeA(smem, row, col, tanh_f(a[0]), tanh_f(a[1]));
                    writeA(smem, row + 8, col, tanh_f(a[2]), tanh_f(a[3]));
                }
        } else {                           // k_{s+1} = h@W2; RK combine -> new A
            const bool fin = (s == 5);
            const float cc = c_cur[s];
#pragma unroll
            for (int mi = 0; mi < 2; mi++)
#pragma unroll
                for (int ni = 0; ni < 4; ni++) {
                    float* a = acc[mi][ni];
                    const int fi = fbase + (mi * 4 + ni) * 128;
                    float4 kc = make_float4(a[0], a[1], a[2], a[3]);
                    if (!fin) *(float4*)&g_k[s][fi] = kc;
                    float4 xv = *(const float4*)&g_x[fi];
                    float4 na;
                    na.x = fmaf(cc, kc.x, xv.x); na.y = fmaf(cc, kc.y, xv.y);
                    na.z = fmaf(cc, kc.z, xv.z); na.w = fmaf(cc, kc.w, xv.w);
#pragma unroll 1
                    for (int sl = 0; sl < 5; sl++) {
                        float cf = c_slot[s][sl];
                        if (cf != 0.0f) {
                            float4 kv = *(const float4*)&g_k[sl][fi];
                            na.x = fmaf(cf, kv.x, na.x); na.y = fmaf(cf, kv.y, na.y);
                            na.z = fmaf(cf, kv.z, na.z); na.w = fmaf(cf, kv.w, na.w);
                        }
                    }
                    int row = mi * 16 + erow, col = ecol + ni * 8;
                    if (fin) {
                        if (g == NGEMM - 1) {   // final x -> out (row/col layout)
                            *(float2*)&out[(growb + row) * DIM + col] = make_float2(na.x, na.y);
                            *(float2*)&out[(growb + row + 8) * DIM + col] = make_float2(na.z, na.w);
                        } else {
                            *(float4*)&g_x[fi] = na;
                        }
                    }
                    writeA(smem, row, col, na.x, na.y);
                    writeA(smem, row + 8, col, na.z, na.w);
                }
        }
        // next gemm's first cp_wait0+__syncthreads orders A writes before ldmatrix
    }
}

extern "C" void kernel_launch(void* const* d_in, const int* in_sizes, int n_in,
                              void* d_out, int out_size) {
    (void)in_sizes; (void)n_in; (void)out_size;
    const float* x0 = (const float*)d_in[0];
    const float* W1 = (const float*)d_in[1];
    const float* W2 = (const float*)d_in[2];
    float* out = (float*)d_out;

    prep_kernel<<<256, 256>>>(W1, W2);
    cudaFuncSetAttribute(ode_hmma_kernel,
                         cudaFuncAttributeMaxDynamicSharedMemorySize, SMEM_BYTES);
    ode_hmma_kernel<<<NCTA, THREADS, SMEM_BYTES>>>(x0, out);
}

// round 9
// speedup vs baseline: 3.1675x; 1.2539x over previous
#include <cuda_runtime.h>
#include <cuda_bf16.h>
#include <cstdint>

// ============================================================================
// Fused dopri5 neural-ODE via mma.sync bf16 (sm_103-safe HMMA path).
// fp32 = bf16 hi/lo split, 3 products. Grid=128 CTAs x 32 rows, 8 warps.
// R8: per-warp W slices (no block barrier for W), 4-deep cp.async pipeline
// (k=32 subchunks, prefetch distance 3), double-buffered A (1 barrier/GEMM),
// x + final-combo accumulator in registers, k5/k6 never stored (4 k slots).
// ============================================================================

#define THREADS   256
#define NSTEPS    40
#define DIM       256
#define BROWS     4096
#define M_CTA     32
#define NCTA      (BROWS / M_CTA)        // 128
#define NGEMM     (NSTEPS * 6 * 2)       // 480
#define NSUB      (NGEMM * 8)            // 3840 k32-subchunks

#define LDA       264                    // A row stride (elements)
#define ABUF_B    (M_CTA * LDA * 2 * 2)  // 33792 (hi plane + lo plane)
#define A_LO      (M_CTA * LDA * 2)      // 16896
#define W_OFF     (2 * ABUF_B)           // 67584
#define WPITCH    80                     // B slice row pitch (bytes), conflict-free
#define WHALF     (32 * WPITCH)          // 2560
#define WSLOT     (2 * WHALF)            // 5120 (hi+lo)
#define WWARP     (4 * WSLOT)            // 20480 per warp
#define SMEM_BYTES (W_OFF + 8 * WWARP)   // 231424

#define FRAG_CTA  (M_CTA * DIM)          // 8192 floats per CTA

__device__ __nv_bfloat16 g_wimg[2 * 2 * 256 * 256]; // [wi][half][n][k]
__device__ float g_k[4][BROWS * DIM];               // k1..k4, fragment layout

__constant__ float c_cur[6] = {
    (float)(0.025 * 0.2), (float)(0.025 * 9.0 / 40.0), (float)(0.025 * 32.0 / 9.0),
    (float)(0.025 * -212.0 / 729.0), (float)(0.025 * -5103.0 / 18656.0),
    (float)(0.025 * 11.0 / 84.0)};                   // s=5: h*b6
__constant__ float c_slot[5][4] = {                  // row s: slot coeffs for y_{s+2}
    {0.f, 0.f, 0.f, 0.f},
    {(float)(0.025 * 3.0 / 40.0), 0.f, 0.f, 0.f},
    {(float)(0.025 * 44.0 / 45.0), (float)(0.025 * -56.0 / 15.0), 0.f, 0.f},
    {(float)(0.025 * 19372.0 / 6561.0), (float)(0.025 * -25360.0 / 2187.0),
     (float)(0.025 * 64448.0 / 6561.0), 0.f},
    {(float)(0.025 * 9017.0 / 3168.0), (float)(0.025 * -355.0 / 33.0),
     (float)(0.025 * 46732.0 / 5247.0), (float)(0.025 * 49.0 / 176.0)}};
__constant__ float c_b[6] = {                        // h * b_j for xacc updates
    (float)(0.025 * 35.0 / 384.0), 0.f, (float)(0.025 * 500.0 / 1113.0),
    (float)(0.025 * 125.0 / 192.0), (float)(0.025 * -2187.0 / 6784.0), 0.f};

__device__ __forceinline__ uint32_t smem_u32(const void* p) {
    uint32_t a;
    asm("{ .reg .u64 t; cvta.to.shared.u64 t, %1; cvt.u32.u64 %0, t; }" : "=r"(a) : "l"(p));
    return a;
}
__device__ __forceinline__ void cp_async16(uint32_t sdst, const void* gsrc) {
    asm volatile("cp.async.cg.shared.global [%0], [%1], 16;\n" ::"r"(sdst), "l"(gsrc));
}
__device__ __forceinline__ void cp_commit() { asm volatile("cp.async.commit_group;\n" ::: "memory"); }
__device__ __forceinline__ void cp_wait3()  { asm volatile("cp.async.wait_group 3;\n" ::: "memory"); }
__device__ __forceinline__ void cp_wait0()  { asm volatile("cp.async.wait_group 0;\n" ::: "memory"); }

__device__ __forceinline__ void ldsm_x4(uint32_t* r, uint32_t addr) {
    asm volatile("ldmatrix.sync.aligned.m8n8.x4.shared.b16 {%0,%1,%2,%3}, [%4];"
                 : "=r"(r[0]), "=r"(r[1]), "=r"(r[2]), "=r"(r[3]) : "r"(addr));
}
__device__ __forceinline__ void mma_bf16(float* c, const uint32_t* a, const uint32_t* b) {
    asm volatile("mma.sync.aligned.m16n8k16.row.col.f32.bf16.bf16.f32 "
                 "{%0,%1,%2,%3}, {%4,%5,%6,%7}, {%8,%9}, {%0,%1,%2,%3};"
                 : "+f"(c[0]), "+f"(c[1]), "+f"(c[2]), "+f"(c[3])
                 : "r"(a[0]), "r"(a[1]), "r"(a[2]), "r"(a[3]), "r"(b[0]), "r"(b[1]));
}

__device__ __forceinline__ float tanh_f(float x) {
    float ax = fabsf(x);
    float e  = __expf(2.0f * ax);
    float t  = 1.0f - 2.0f / (e + 1.0f);
    return copysignf(t, x);
}
__device__ __forceinline__ uint32_t bpack(float a, float b) {
    __nv_bfloat162 h = __floats2bfloat162_rn(a, b);
    return *(uint32_t*)&h;
}
__device__ __forceinline__ void writeA(uint32_t sb, int buf, int row, int col,
                                       float a, float b) {
    float ah = __bfloat162float(__float2bfloat16(a));
    float bh = __bfloat162float(__float2bfloat16(b));
    uint32_t off = sb + (uint32_t)buf * ABUF_B + (uint32_t)(row * LDA + col) * 2;
    asm volatile("st.shared.b32 [%0], %1;" :: "r"(off), "r"(bpack(ah, bh)) : "memory");
    asm volatile("st.shared.b32 [%0], %1;" :: "r"(off + A_LO), "r"(bpack(a - ah, b - bh)) : "memory");
}

__global__ void prep_kernel(const float* __restrict__ W1, const float* __restrict__ W2) {
    int e = blockIdx.x * blockDim.x + threadIdx.x;   // k*256 + n
    int k = e >> 8, n = e & 255;
#pragma unroll
    for (int wi = 0; wi < 2; wi++) {
        float v = (wi ? W2 : W1)[k * 256 + n];
        __nv_bfloat16 hi = __float2bfloat16(v);
        float lo = v - __bfloat162float(hi);
        g_wimg[((wi * 2 + 0) << 16) + n * 256 + k] = hi;
        g_wimg[((wi * 2 + 1) << 16) + n * 256 + k] = __float2bfloat16(lo);
    }
}

__device__ __forceinline__ void load_slice(uint32_t sb, int ci, int warp, int lane) {
    const int g = ci >> 3, wi = g & 1, sub = ci & 7;
    const uint32_t dst = sb + W_OFF + (uint32_t)warp * WWARP + (uint32_t)(ci & 3) * WSLOT;
#pragma unroll
    for (int i = 0; i < 8; i++) {
        int idx = lane + i * 32;                     // 0..255
        int half = idx >> 7, r = (idx >> 2) & 31, seg = idx & 3;
        const __nv_bfloat16* src = g_wimg +
            (((wi * 2 + half) << 16) + (warp * 32 + r) * 256 + sub * 32 + seg * 8);
        cp_async16(dst + half * WHALF + r * WPITCH + seg * 16, src);
    }
    cp_commit();
}

__global__ void __launch_bounds__(THREADS, 1)
ode_hmma_kernel(const float* __restrict__ x0, float* __restrict__ out) {
    extern __shared__ __align__(16) char smem[];
    const uint32_t sb = smem_u32(smem);
    const int tid = threadIdx.x, warp = tid >> 5, lane = tid & 31;
    const int quad = lane >> 3, lrow = lane & 7;

    const int a_row  = lrow + ((quad & 1) << 3);
    const int a_col8 = (quad >> 1) << 3;
    const int b_row  = lrow + ((quad >> 1) << 3);
    const int b_kadd = (quad & 1) << 3;

    const int erow = lane >> 2;
    const int ecol = warp * 32 + 2 * (lane & 3);
    const int fbase = blockIdx.x * FRAG_CTA + warp * 1024 + lane * 4;
    const int growb = blockIdx.x * M_CTA;

    float4 xreg[8], xacc[8];

#pragma unroll
    for (int mi = 0; mi < 2; mi++)
#pragma unroll
        for (int ni = 0; ni < 4; ni++) {
            int row = mi * 16 + erow, col = ecol + ni * 8;
            float2 v01 = *(const float2*)&x0[(growb + row) * DIM + col];
            float2 v23 = *(const float2*)&x0[(growb + row + 8) * DIM + col];
            xreg[mi * 4 + ni] = make_float4(v01.x, v01.y, v23.x, v23.y);
            writeA(sb, 0, row, col, v01.x, v01.y);
            writeA(sb, 0, row + 8, col, v23.x, v23.y);
        }

#pragma unroll
    for (int i = 0; i < 4; i++) load_slice(sb, i, warp, lane);

    __syncthreads();

    float acc[2][4][4];
#pragma unroll 1
    for (int g = 0; g < NGEMM; g++) {
        const int s = (g >> 1) % 6, j = g & 1;
        const uint32_t abase = sb + (uint32_t)(g & 1) * ABUF_B;
#pragma unroll
        for (int mi = 0; mi < 2; mi++)
#pragma unroll
            for (int ni = 0; ni < 4; ni++)
#pragma unroll
                for (int c = 0; c < 4; c++) acc[mi][ni][c] = 0.0f;

#pragma unroll 1
        for (int sub = 0; sub < 8; sub++) {
            const int ci = g * 8 + sub;
            if (ci + 4 < NSUB) cp_wait3(); else cp_wait0();
            __syncwarp();
            const uint32_t wsl = sb + W_OFF + (uint32_t)warp * WWARP +
                                 (uint32_t)(ci & 3) * WSLOT;
#pragma unroll
            for (int kq = 0; kq < 2; kq++) {
                const int kg = sub * 32 + kq * 16;
                uint32_t ahi[2][4], alo[2][4], bhi[8], blo[8];
#pragma unroll
                for (int mi = 0; mi < 2; mi++) {
                    uint32_t ao = abase + (uint32_t)(((mi * 16 + a_row) * LDA + kg + a_col8) * 2);
                    ldsm_x4(ahi[mi], ao);
                    ldsm_x4(alo[mi], ao + A_LO);
                }
#pragma unroll
                for (int np = 0; np < 2; np++) {
                    uint32_t bo = wsl + (uint32_t)((np * 16 + b_row) * WPITCH +
                                                   (kq * 16 + b_kadd) * 2);
                    ldsm_x4(&bhi[np * 4], bo);
                    ldsm_x4(&blo[np * 4], bo + WHALF);
                }
#pragma unroll
                for (int mi = 0; mi < 2; mi++)
#pragma unroll
                    for (int ni = 0; ni < 4; ni++) {
                        mma_bf16(acc[mi][ni], ahi[mi], &bhi[ni * 2]);  // hi*hi
                        mma_bf16(acc[mi][ni], alo[mi], &bhi[ni * 2]);  // lo*hi
                        mma_bf16(acc[mi][ni], ahi[mi], &blo[ni * 2]);  // hi*lo
                    }
            }
            if (ci + 4 < NSUB) load_slice(sb, ci + 4, warp, lane);
        }

        const int nbuf = (g + 1) & 1;
        if (j == 0) {
#pragma unroll
            for (int mi = 0; mi < 2; mi++)
#pragma unroll
                for (int ni = 0; ni < 4; ni++) {
                    float* a = acc[mi][ni];
                    int row = mi * 16 + erow, col = ecol + ni * 8;
                    writeA(sb, nbuf, row, col, tanh_f(a[0]), tanh_f(a[1]));
                    writeA(sb, nbuf, row + 8, col, tanh_f(a[2]), tanh_f(a[3]));
                }
        } else {
            const bool fin = (s == 5);
            const float cc = c_cur[s];
            const float cb = c_b[s];
#pragma unroll
            for (int mi = 0; mi < 2; mi++)
#pragma unroll
                for (int ni = 0; ni < 4; ni++) {
                    float* a = acc[mi][ni];
                    const int idx = mi * 4 + ni;
                    const int fi = fbase + idx * 128;
                    float4 kc = make_float4(a[0], a[1], a[2], a[3]);
                    if (s <= 3) *(float4*)&g_k[s][fi] = kc;
                    float4 xv = xreg[idx];
                    if (s == 0) {
                        xacc[idx] = make_float4(fmaf(cb, kc.x, xv.x), fmaf(cb, kc.y, xv.y),
                                                fmaf(cb, kc.z, xv.z), fmaf(cb, kc.w, xv.w));
                    } else if (cb != 0.0f) {
                        float4 t = xacc[idx];
                        xacc[idx] = make_float4(fmaf(cb, kc.x, t.x), fmaf(cb, kc.y, t.y),
                                                fmaf(cb, kc.z, t.z), fmaf(cb, kc.w, t.w));
                    }
                    float4 na;
                    if (!fin) {            // y_{s+2} = x + cc*k_cur + sum slots
                        na = make_float4(fmaf(cc, kc.x, xv.x), fmaf(cc, kc.y, xv.y),
                                         fmaf(cc, kc.z, xv.z), fmaf(cc, kc.w, xv.w));
#pragma unroll 1
                        for (int sl = 0; sl < 4; sl++) {
                            float cf = c_slot[s][sl];
                            if (cf != 0.0f) {
                                float4 kv = *(const float4*)&g_k[sl][fi];
                                na.x = fmaf(cf, kv.x, na.x); na.y = fmaf(cf, kv.y, na.y);
                                na.z = fmaf(cf, kv.z, na.z); na.w = fmaf(cf, kv.w, na.w);
                            }
                        }
                    } else {               // new x = xacc + h*b6*k6
                        float4 t = xacc[idx];
                        na = make_float4(fmaf(cc, kc.x, t.x), fmaf(cc, kc.y, t.y),
                                         fmaf(cc, kc.z, t.z), fmaf(cc, kc.w, t.w));
                        xreg[idx] = na;
                    }
                    int row = mi * 16 + erow, col = ecol + ni * 8;
                    if (g == NGEMM - 1) {
                        *(float2*)&out[(growb + row) * DIM + col] = make_float2(na.x, na.y);
                        *(float2*)&out[(growb + row + 8) * DIM + col] = make_float2(na.z, na.w);
                    } else {
                        writeA(sb, nbuf, row, col, na.x, na.y);
                        writeA(sb, nbuf, row + 8, col, na.z, na.w);
                    }
                }
        }
        __syncthreads();   // publish A buffer (g+1)&1
    }
}

extern "C" void kernel_launch(void* const* d_in, const int* in_sizes, int n_in,
                              void* d_out, int out_size) {
    (void)in_sizes; (void)n_in; (void)out_size;
    const float* x0 = (const float*)d_in[0];
    const float* W1 = (const float*)d_in[1];
    const float* W2 = (const float*)d_in[2];
    float* out = (float*)d_out;

    prep_kernel<<<256, 256>>>(W1, W2);
    cudaFuncSetAttribute(ode_hmma_kernel,
                         cudaFuncAttributeMaxDynamicSharedMemorySize, SMEM_BYTES);
    ode_hmma_kernel<<<NCTA, THREADS, SMEM_BYTES>>>(x0, out);
}

// round 10
// speedup vs baseline: 4.0206x; 1.2694x over previous
#include <cuda_runtime.h>
#include <cuda_bf16.h>
#include <cstdint>

// ============================================================================
// Fused dopri5 neural-ODE via mma.sync bf16 (sm_103-safe HMMA path).
// fp32 = bf16 hi/lo split, 3 products. Grid=128 CTAs x 32 rows.
// R9: 512 threads / 16 warps (4 warps/SMSP, was 2) - warp N-strip 16.
// Per-warp W slices + 4-deep cp.async ring, double-buffered A (1 barrier/GEMM),
// x + final-combo accumulator in registers, k5/k6 never stored.
// ============================================================================

#define THREADS   512
#define NWARP     16
#define NSTEPS    40
#define DIM       256
#define BROWS     4096
#define M_CTA     32
#define NCTA      (BROWS / M_CTA)        // 128
#define NGEMM     (NSTEPS * 6 * 2)       // 480
#define NSUB      (NGEMM * 8)            // 3840 k32-subchunks

#define LDA       264                    // A row stride (elements)
#define ABUF_B    (M_CTA * LDA * 2 * 2)  // 33792 (hi plane + lo plane)
#define A_LO      (M_CTA * LDA * 2)      // 16896
#define W_OFF     (2 * ABUF_B)           // 67584
#define WPITCH    80                     // B slice row pitch (bytes)
#define WHALF     (16 * WPITCH)          // 1280 (16 rows per warp)
#define WSLOT     (2 * WHALF)            // 2560 (hi+lo)
#define WWARP     (4 * WSLOT)            // 10240 per warp
#define SMEM_BYTES (W_OFF + NWARP * WWARP) // 231424

#define FRAG_CTA  (M_CTA * DIM)          // 8192 floats per CTA

__device__ __nv_bfloat16 g_wimg[2 * 2 * 256 * 256]; // [wi][half][n][k]
__device__ float g_k[4][BROWS * DIM];               // k1..k4, fragment layout

__constant__ float c_cur[6] = {
    (float)(0.025 * 0.2), (float)(0.025 * 9.0 / 40.0), (float)(0.025 * 32.0 / 9.0),
    (float)(0.025 * -212.0 / 729.0), (float)(0.025 * -5103.0 / 18656.0),
    (float)(0.025 * 11.0 / 84.0)};                   // s=5: h*b6
__constant__ float c_slot[5][4] = {                  // row s: slot coeffs for y_{s+2}
    {0.f, 0.f, 0.f, 0.f},
    {(float)(0.025 * 3.0 / 40.0), 0.f, 0.f, 0.f},
    {(float)(0.025 * 44.0 / 45.0), (float)(0.025 * -56.0 / 15.0), 0.f, 0.f},
    {(float)(0.025 * 19372.0 / 6561.0), (float)(0.025 * -25360.0 / 2187.0),
     (float)(0.025 * 64448.0 / 6561.0), 0.f},
    {(float)(0.025 * 9017.0 / 3168.0), (float)(0.025 * -355.0 / 33.0),
     (float)(0.025 * 46732.0 / 5247.0), (float)(0.025 * 49.0 / 176.0)}};
__constant__ float c_b[6] = {                        // h * b_j for xacc updates
    (float)(0.025 * 35.0 / 384.0), 0.f, (float)(0.025 * 500.0 / 1113.0),
    (float)(0.025 * 125.0 / 192.0), (float)(0.025 * -2187.0 / 6784.0), 0.f};

__device__ __forceinline__ uint32_t smem_u32(const void* p) {
    uint32_t a;
    asm("{ .reg .u64 t; cvta.to.shared.u64 t, %1; cvt.u32.u64 %0, t; }" : "=r"(a) : "l"(p));
    return a;
}
__device__ __forceinline__ void cp_async16(uint32_t sdst, const void* gsrc) {
    asm volatile("cp.async.cg.shared.global [%0], [%1], 16;\n" ::"r"(sdst), "l"(gsrc));
}
__device__ __forceinline__ void cp_commit() { asm volatile("cp.async.commit_group;\n" ::: "memory"); }
__device__ __forceinline__ void cp_wait3()  { asm volatile("cp.async.wait_group 3;\n" ::: "memory"); }
__device__ __forceinline__ void cp_wait0()  { asm volatile("cp.async.wait_group 0;\n" ::: "memory"); }

__device__ __forceinline__ void ldsm_x4(uint32_t* r, uint32_t addr) {
    asm volatile("ldmatrix.sync.aligned.m8n8.x4.shared.b16 {%0,%1,%2,%3}, [%4];"
                 : "=r"(r[0]), "=r"(r[1]), "=r"(r[2]), "=r"(r[3]) : "r"(addr));
}
__device__ __forceinline__ void mma_bf16(float* c, const uint32_t* a, const uint32_t* b) {
    asm volatile("mma.sync.aligned.m16n8k16.row.col.f32.bf16.bf16.f32 "
                 "{%0,%1,%2,%3}, {%4,%5,%6,%7}, {%8,%9}, {%0,%1,%2,%3};"
                 : "+f"(c[0]), "+f"(c[1]), "+f"(c[2]), "+f"(c[3])
                 : "r"(a[0]), "r"(a[1]), "r"(a[2]), "r"(a[3]), "r"(b[0]), "r"(b[1]));
}

__device__ __forceinline__ float tanh_f(float x) {
    float ax = fabsf(x);
    float e  = __expf(2.0f * ax);
    float t  = 1.0f - 2.0f / (e + 1.0f);
    return copysignf(t, x);
}
__device__ __forceinline__ uint32_t bpack(float a, float b) {
    __nv_bfloat162 h = __floats2bfloat162_rn(a, b);
    return *(uint32_t*)&h;
}
__device__ __forceinline__ void writeA(uint32_t sb, int buf, int row, int col,
                                       float a, float b) {
    float ah = __bfloat162float(__float2bfloat16(a));
    float bh = __bfloat162float(__float2bfloat16(b));
    uint32_t off = sb + (uint32_t)buf * ABUF_B + (uint32_t)(row * LDA + col) * 2;
    asm volatile("st.shared.b32 [%0], %1;" :: "r"(off), "r"(bpack(ah, bh)) : "memory");
    asm volatile("st.shared.b32 [%0], %1;" :: "r"(off + A_LO), "r"(bpack(a - ah, b - bh)) : "memory");
}

__global__ void prep_kernel(const float* __restrict__ W1, const float* __restrict__ W2) {
    int e = blockIdx.x * blockDim.x + threadIdx.x;   // k*256 + n
    int k = e >> 8, n = e & 255;
#pragma unroll
    for (int wi = 0; wi < 2; wi++) {
        float v = (wi ? W2 : W1)[k * 256 + n];
        __nv_bfloat16 hi = __float2bfloat16(v);
        float lo = v - __bfloat162float(hi);
        g_wimg[((wi * 2 + 0) << 16) + n * 256 + k] = hi;
        g_wimg[((wi * 2 + 1) << 16) + n * 256 + k] = __float2bfloat16(lo);
    }
}

// per-warp: load this warp's 16 B-rows for subchunk ci (k=32 span, hi+lo = 2KB)
__device__ __forceinline__ void load_slice(uint32_t sb, int ci, int warp, int lane) {
    const int g = ci >> 3, wi = g & 1, sub = ci & 7;
    const uint32_t dst = sb + W_OFF + (uint32_t)warp * WWARP + (uint32_t)(ci & 3) * WSLOT;
#pragma unroll
    for (int i = 0; i < 4; i++) {
        int idx = lane + i * 32;                     // 0..127
        int half = idx >> 6, r = (idx >> 2) & 15, seg = idx & 3;
        const __nv_bfloat16* src = g_wimg +
            (((wi * 2 + half) << 16) + (warp * 16 + r) * 256 + sub * 32 + seg * 8);
        cp_async16(dst + half * WHALF + r * WPITCH + seg * 16, src);
    }
    cp_commit();
}

__global__ void __launch_bounds__(THREADS, 1)
ode_hmma_kernel(const float* __restrict__ x0, float* __restrict__ out) {
    extern __shared__ __align__(16) char smem[];
    const uint32_t sb = smem_u32(smem);
    const int tid = threadIdx.x, warp = tid >> 5, lane = tid & 31;
    const int quad = lane >> 3, lrow = lane & 7;

    const int a_row  = lrow + ((quad & 1) << 3);
    const int a_col8 = (quad >> 1) << 3;
    const int b_row  = lrow + ((quad >> 1) << 3);    // 16 rows of this warp's strip
    const int b_kadd = (quad & 1) << 3;

    const int erow = lane >> 2;
    const int ecol = warp * 16 + 2 * (lane & 3);     // + ni*8
    const int fbase = blockIdx.x * FRAG_CTA + warp * 512 + lane * 4;
    const int growb = blockIdx.x * M_CTA;

    float4 xreg[4], xacc[4];

    // ---- init: x0 -> x regs and A buffer 0 ----
#pragma unroll
    for (int mi = 0; mi < 2; mi++)
#pragma unroll
        for (int ni = 0; ni < 2; ni++) {
            int row = mi * 16 + erow, col = ecol + ni * 8;
            float2 v01 = *(const float2*)&x0[(growb + row) * DIM + col];
            float2 v23 = *(const float2*)&x0[(growb + row + 8) * DIM + col];
            xreg[mi * 2 + ni] = make_float4(v01.x, v01.y, v23.x, v23.y);
            writeA(sb, 0, row, col, v01.x, v01.y);
            writeA(sb, 0, row + 8, col, v23.x, v23.y);
        }

#pragma unroll
    for (int i = 0; i < 4; i++) load_slice(sb, i, warp, lane);

    __syncthreads();

    float acc[2][2][4];
#pragma unroll 1
    for (int g = 0; g < NGEMM; g++) {
        const int s = (g >> 1) % 6, j = g & 1;
        const uint32_t abase = sb + (uint32_t)(g & 1) * ABUF_B;
#pragma unroll
        for (int mi = 0; mi < 2; mi++)
#pragma unroll
            for (int ni = 0; ni < 2; ni++)
#pragma unroll
                for (int c = 0; c < 4; c++) acc[mi][ni][c] = 0.0f;

#pragma unroll 1
        for (int sub = 0; sub < 8; sub++) {
            const int ci = g * 8 + sub;
            if (ci + 4 < NSUB) cp_wait3(); else cp_wait0();
            __syncwarp();
            const uint32_t wsl = sb + W_OFF + (uint32_t)warp * WWARP +
                                 (uint32_t)(ci & 3) * WSLOT;
#pragma unroll
            for (int kq = 0; kq < 2; kq++) {
                const int kg = sub * 32 + kq * 16;
                uint32_t ahi[2][4], alo[2][4], bhi[4], blo[4];
#pragma unroll
                for (int mi = 0; mi < 2; mi++) {
                    uint32_t ao = abase + (uint32_t)(((mi * 16 + a_row) * LDA + kg + a_col8) * 2);
                    ldsm_x4(ahi[mi], ao);
                    ldsm_x4(alo[mi], ao + A_LO);
                }
                {
                    uint32_t bo = wsl + (uint32_t)(b_row * WPITCH + (kq * 16 + b_kadd) * 2);
                    ldsm_x4(bhi, bo);
                    ldsm_x4(blo, bo + WHALF);
                }
#pragma unroll
                for (int mi = 0; mi < 2; mi++)
#pragma unroll
                    for (int ni = 0; ni < 2; ni++) {
                        mma_bf16(acc[mi][ni], ahi[mi], &bhi[ni * 2]);  // hi*hi
                        mma_bf16(acc[mi][ni], alo[mi], &bhi[ni * 2]);  // lo*hi
                        mma_bf16(acc[mi][ni], ahi[mi], &blo[ni * 2]);  // hi*lo
                    }
            }
            if (ci + 4 < NSUB) load_slice(sb, ci + 4, warp, lane);
        }

        // ---- epilogue -> A buffer (g+1)&1 ----
        const int nbuf = (g + 1) & 1;
        if (j == 0) {                      // h = tanh(x@W1)
#pragma unroll
            for (int mi = 0; mi < 2; mi++)
#pragma unroll
                for (int ni = 0; ni < 2; ni++) {
                    float* a = acc[mi][ni];
                    int row = mi * 16 + erow, col = ecol + ni * 8;
                    writeA(sb, nbuf, row, col, tanh_f(a[0]), tanh_f(a[1]));
                    writeA(sb, nbuf, row + 8, col, tanh_f(a[2]), tanh_f(a[3]));
                }
        } else {                           // k_{s+1} = h@W2; RK update
            const bool fin = (s == 5);
            const float cc = c_cur[s];
            const float cb = c_b[s];
#pragma unroll
            for (int mi = 0; mi < 2; mi++)
#pragma unroll
                for (int ni = 0; ni < 2; ni++) {
                    float* a = acc[mi][ni];
                    const int idx = mi * 2 + ni;
                    const int fi = fbase + idx * 128;
                    float4 kc = make_float4(a[0], a[1], a[2], a[3]);
                    if (s <= 3) *(float4*)&g_k[s][fi] = kc;
                    float4 xv = xreg[idx];
                    if (s == 0) {
                        xacc[idx] = make_float4(fmaf(cb, kc.x, xv.x), fmaf(cb, kc.y, xv.y),
                                                fmaf(cb, kc.z, xv.z), fmaf(cb, kc.w, xv.w));
                    } else if (cb != 0.0f) {
                        float4 t = xacc[idx];
                        xacc[idx] = make_float4(fmaf(cb, kc.x, t.x), fmaf(cb, kc.y, t.y),
                                                fmaf(cb, kc.z, t.z), fmaf(cb, kc.w, t.w));
                    }
                    float4 na;
                    if (!fin) {            // y_{s+2} = x + cc*k_cur + sum slots
                        na = make_float4(fmaf(cc, kc.x, xv.x), fmaf(cc, kc.y, xv.y),
                                         fmaf(cc, kc.z, xv.z), fmaf(cc, kc.w, xv.w));
#pragma unroll 1
                        for (int sl = 0; sl < 4; sl++) {
                            float cf = c_slot[s][sl];
                            if (cf != 0.0f) {
                                float4 kv = *(const float4*)&g_k[sl][fi];
                                na.x = fmaf(cf, kv.x, na.x); na.y = fmaf(cf, kv.y, na.y);
                                na.z = fmaf(cf, kv.z, na.z); na.w = fmaf(cf, kv.w, na.w);
                            }
                        }
                    } else {               // new x = xacc + h*b6*k6
                        float4 t = xacc[idx];
                        na = make_float4(fmaf(cc, kc.x, t.x), fmaf(cc, kc.y, t.y),
                                         fmaf(cc, kc.z, t.z), fmaf(cc, kc.w, t.w));
                        xreg[idx] = na;
                    }
                    int row = mi * 16 + erow, col = ecol + ni * 8;
                    if (g == NGEMM - 1) {
                        *(float2*)&out[(growb + row) * DIM + col] = make_float2(na.x, na.y);
                        *(float2*)&out[(growb + row + 8) * DIM + col] = make_float2(na.z, na.w);
                    } else {
                        writeA(sb, nbuf, row, col, na.x, na.y);
                        writeA(sb, nbuf, row + 8, col, na.z, na.w);
                    }
                }
        }
        __syncthreads();   // publish A buffer (g+1)&1
    }
}

extern "C" void kernel_launch(void* const* d_in, const int* in_sizes, int n_in,
                              void* d_out, int out_size) {
    (void)in_sizes; (void)n_in; (void)out_size;
    const float* x0 = (const float*)d_in[0];
    const float* W1 = (const float*)d_in[1];
    const float* W2 = (const float*)d_in[2];
    float* out = (float*)d_out;

    prep_kernel<<<256, 256>>>(W1, W2);
    cudaFuncSetAttribute(ode_hmma_kernel,
                         cudaFuncAttributeMaxDynamicSharedMemorySize, SMEM_BYTES);
    ode_hmma_kernel<<<NCTA, THREADS, SMEM_BYTES>>>(x0, out);
}

// round 11
// speedup vs baseline: 4.6358x; 1.1530x over previous
#include <cuda_runtime.h>
#include <cuda_bf16.h>
#include <cstdint>

// ============================================================================
// Fused dopri5 neural-ODE via mma.sync bf16 (sm_103-safe HMMA path).
// fp32 = bf16 hi/lo split, 3 products. Grid=128 CTAs x 32 rows, 16 warps.
// R10: dual accumulators (hi*hi vs corrections) to break HMMA RAW chains;
// div.approx tanh; batched predicated k-slot loads in the RK epilogue.
// ============================================================================

#define THREADS   512
#define NWARP     16
#define NSTEPS    40
#define DIM       256
#define BROWS     4096
#define M_CTA     32
#define NCTA      (BROWS / M_CTA)        // 128
#define NGEMM     (NSTEPS * 6 * 2)       // 480
#define NSUB      (NGEMM * 8)            // 3840 k32-subchunks

#define LDA       264                    // A row stride (elements)
#define ABUF_B    (M_CTA * LDA * 2 * 2)  // 33792 (hi plane + lo plane)
#define A_LO      (M_CTA * LDA * 2)      // 16896
#define W_OFF     (2 * ABUF_B)           // 67584
#define WPITCH    80                     // B slice row pitch (bytes)
#define WHALF     (16 * WPITCH)          // 1280 (16 rows per warp)
#define WSLOT     (2 * WHALF)            // 2560 (hi+lo)
#define WWARP     (4 * WSLOT)            // 10240 per warp
#define SMEM_BYTES (W_OFF + NWARP * WWARP) // 231424

#define FRAG_CTA  (M_CTA * DIM)          // 8192 floats per CTA

__device__ __nv_bfloat16 g_wimg[2 * 2 * 256 * 256]; // [wi][half][n][k]
__device__ float g_k[4][BROWS * DIM];               // k1..k4, fragment layout

__constant__ float c_cur[6] = {
    (float)(0.025 * 0.2), (float)(0.025 * 9.0 / 40.0), (float)(0.025 * 32.0 / 9.0),
    (float)(0.025 * -212.0 / 729.0), (float)(0.025 * -5103.0 / 18656.0),
    (float)(0.025 * 11.0 / 84.0)};                   // s=5: h*b6
__constant__ float c_slot[5][4] = {                  // row s: slot coeffs for y_{s+2}
    {0.f, 0.f, 0.f, 0.f},
    {(float)(0.025 * 3.0 / 40.0), 0.f, 0.f, 0.f},
    {(float)(0.025 * 44.0 / 45.0), (float)(0.025 * -56.0 / 15.0), 0.f, 0.f},
    {(float)(0.025 * 19372.0 / 6561.0), (float)(0.025 * -25360.0 / 2187.0),
     (float)(0.025 * 64448.0 / 6561.0), 0.f},
    {(float)(0.025 * 9017.0 / 3168.0), (float)(0.025 * -355.0 / 33.0),
     (float)(0.025 * 46732.0 / 5247.0), (float)(0.025 * 49.0 / 176.0)}};
__constant__ float c_b[6] = {                        // h * b_j for xacc updates
    (float)(0.025 * 35.0 / 384.0), 0.f, (float)(0.025 * 500.0 / 1113.0),
    (float)(0.025 * 125.0 / 192.0), (float)(0.025 * -2187.0 / 6784.0), 0.f};

__device__ __forceinline__ uint32_t smem_u32(const void* p) {
    uint32_t a;
    asm("{ .reg .u64 t; cvta.to.shared.u64 t, %1; cvt.u32.u64 %0, t; }" : "=r"(a) : "l"(p));
    return a;
}
__device__ __forceinline__ void cp_async16(uint32_t sdst, const void* gsrc) {
    asm volatile("cp.async.cg.shared.global [%0], [%1], 16;\n" ::"r"(sdst), "l"(gsrc));
}
__device__ __forceinline__ void cp_commit() { asm volatile("cp.async.commit_group;\n" ::: "memory"); }
__device__ __forceinline__ void cp_wait3()  { asm volatile("cp.async.wait_group 3;\n" ::: "memory"); }
__device__ __forceinline__ void cp_wait0()  { asm volatile("cp.async.wait_group 0;\n" ::: "memory"); }

__device__ __forceinline__ void ldsm_x4(uint32_t* r, uint32_t addr) {
    asm volatile("ldmatrix.sync.aligned.m8n8.x4.shared.b16 {%0,%1,%2,%3}, [%4];"
                 : "=r"(r[0]), "=r"(r[1]), "=r"(r[2]), "=r"(r[3]) : "r"(addr));
}
__device__ __forceinline__ void mma_bf16(float* c, const uint32_t* a, const uint32_t* b) {
    asm volatile("mma.sync.aligned.m16n8k16.row.col.f32.bf16.bf16.f32 "
                 "{%0,%1,%2,%3}, {%4,%5,%6,%7}, {%8,%9}, {%0,%1,%2,%3};"
                 : "+f"(c[0]), "+f"(c[1]), "+f"(c[2]), "+f"(c[3])
                 : "r"(a[0]), "r"(a[1]), "r"(a[2]), "r"(a[3]), "r"(b[0]), "r"(b[1]));
}

// fast precise-enough tanh: ex2-approx exp + div.approx (~2 ulp)
__device__ __forceinline__ float tanh_f(float x) {
    float ax = fabsf(x);
    float e  = __expf(2.0f * ax);            // inf for large ax -> r = 0 -> t = 1
    float r  = __fdividef(2.0f, e + 1.0f);
    return copysignf(1.0f - r, x);
}
__device__ __forceinline__ uint32_t bpack(float a, float b) {
    __nv_bfloat162 h = __floats2bfloat162_rn(a, b);
    return *(uint32_t*)&h;
}
__device__ __forceinline__ void writeA(uint32_t sb, int buf, int row, int col,
                                       float a, float b) {
    float ah = __bfloat162float(__float2bfloat16(a));
    float bh = __bfloat162float(__float2bfloat16(b));
    uint32_t off = sb + (uint32_t)buf * ABUF_B + (uint32_t)(row * LDA + col) * 2;
    asm volatile("st.shared.b32 [%0], %1;" :: "r"(off), "r"(bpack(ah, bh)) : "memory");
    asm volatile("st.shared.b32 [%0], %1;" :: "r"(off + A_LO), "r"(bpack(a - ah, b - bh)) : "memory");
}

__global__ void prep_kernel(const float* __restrict__ W1, const float* __restrict__ W2) {
    int e = blockIdx.x * blockDim.x + threadIdx.x;   // k*256 + n
    int k = e >> 8, n = e & 255;
#pragma unroll
    for (int wi = 0; wi < 2; wi++) {
        float v = (wi ? W2 : W1)[k * 256 + n];
        __nv_bfloat16 hi = __float2bfloat16(v);
        float lo = v - __bfloat162float(hi);
        g_wimg[((wi * 2 + 0) << 16) + n * 256 + k] = hi;
        g_wimg[((wi * 2 + 1) << 16) + n * 256 + k] = __float2bfloat16(lo);
    }
}

// per-warp: load this warp's 16 B-rows for subchunk ci (k=32 span, hi+lo = 2KB)
__device__ __forceinline__ void load_slice(uint32_t sb, int ci, int warp, int lane) {
    const int g = ci >> 3, wi = g & 1, sub = ci & 7;
    const uint32_t dst = sb + W_OFF + (uint32_t)warp * WWARP + (uint32_t)(ci & 3) * WSLOT;
#pragma unroll
    for (int i = 0; i < 4; i++) {
        int idx = lane + i * 32;                     // 0..127
        int half = idx >> 6, r = (idx >> 2) & 15, seg = idx & 3;
        const __nv_bfloat16* src = g_wimg +
            (((wi * 2 + half) << 16) + (warp * 16 + r) * 256 + sub * 32 + seg * 8);
        cp_async16(dst + half * WHALF + r * WPITCH + seg * 16, src);
    }
    cp_commit();
}

__global__ void __launch_bounds__(THREADS, 1)
ode_hmma_kernel(const float* __restrict__ x0, float* __restrict__ out) {
    extern __shared__ __align__(16) char smem[];
    const uint32_t sb = smem_u32(smem);
    const int tid = threadIdx.x, warp = tid >> 5, lane = tid & 31;
    const int quad = lane >> 3, lrow = lane & 7;

    const int a_row  = lrow + ((quad & 1) << 3);
    const int a_col8 = (quad >> 1) << 3;
    const int b_row  = lrow + ((quad >> 1) << 3);    // 16 rows of this warp's strip
    const int b_kadd = (quad & 1) << 3;

    const int erow = lane >> 2;
    const int ecol = warp * 16 + 2 * (lane & 3);     // + ni*8
    const int fbase = blockIdx.x * FRAG_CTA + warp * 512 + lane * 4;
    const int growb = blockIdx.x * M_CTA;

    float4 xreg[4], xacc[4];

    // ---- init: x0 -> x regs and A buffer 0 ----
#pragma unroll
    for (int mi = 0; mi < 2; mi++)
#pragma unroll
        for (int ni = 0; ni < 2; ni++) {
            int row = mi * 16 + erow, col = ecol + ni * 8;
            float2 v01 = *(const float2*)&x0[(growb + row) * DIM + col];
            float2 v23 = *(const float2*)&x0[(growb + row + 8) * DIM + col];
            xreg[mi * 2 + ni] = make_float4(v01.x, v01.y, v23.x, v23.y);
            writeA(sb, 0, row, col, v01.x, v01.y);
            writeA(sb, 0, row + 8, col, v23.x, v23.y);
        }

#pragma unroll
    for (int i = 0; i < 4; i++) load_slice(sb, i, warp, lane);

    __syncthreads();

    float accA[2][2][4], accB[2][2][4];
#pragma unroll 1
    for (int g = 0; g < NGEMM; g++) {
        const int s = (g >> 1) % 6, j = g & 1;
        const uint32_t abase = sb + (uint32_t)(g & 1) * ABUF_B;
#pragma unroll
        for (int mi = 0; mi < 2; mi++)
#pragma unroll
            for (int ni = 0; ni < 2; ni++)
#pragma unroll
                for (int c = 0; c < 4; c++) {
                    accA[mi][ni][c] = 0.0f;
                    accB[mi][ni][c] = 0.0f;
                }

#pragma unroll 1
        for (int sub = 0; sub < 8; sub++) {
            const int ci = g * 8 + sub;
            if (ci + 4 < NSUB) cp_wait3(); else cp_wait0();
            __syncwarp();
            const uint32_t wsl = sb + W_OFF + (uint32_t)warp * WWARP +
                                 (uint32_t)(ci & 3) * WSLOT;
#pragma unroll
            for (int kq = 0; kq < 2; kq++) {
                const int kg = sub * 32 + kq * 16;
                uint32_t ahi[2][4], alo[2][4], bhi[4], blo[4];
#pragma unroll
                for (int mi = 0; mi < 2; mi++) {
                    uint32_t ao = abase + (uint32_t)(((mi * 16 + a_row) * LDA + kg + a_col8) * 2);
                    ldsm_x4(ahi[mi], ao);
                    ldsm_x4(alo[mi], ao + A_LO);
                }
                {
                    uint32_t bo = wsl + (uint32_t)(b_row * WPITCH + (kq * 16 + b_kadd) * 2);
                    ldsm_x4(bhi, bo);
                    ldsm_x4(blo, bo + WHALF);
                }
                // hi*hi into accA (chain 1/frag); corrections into accB (chain 2/frag)
#pragma unroll
                for (int mi = 0; mi < 2; mi++)
#pragma unroll
                    for (int ni = 0; ni < 2; ni++) {
                        mma_bf16(accA[mi][ni], ahi[mi], &bhi[ni * 2]);  // hi*hi
                        mma_bf16(accB[mi][ni], alo[mi], &bhi[ni * 2]);  // lo*hi
                        mma_bf16(accB[mi][ni], ahi[mi], &blo[ni * 2]);  // hi*lo
                    }
            }
            if (ci + 4 < NSUB) load_slice(sb, ci + 4, warp, lane);
        }

        // ---- epilogue -> A buffer (g+1)&1 ----
        const int nbuf = (g + 1) & 1;
        if (j == 0) {                      // h = tanh(x@W1)
#pragma unroll
            for (int mi = 0; mi < 2; mi++)
#pragma unroll
                for (int ni = 0; ni < 2; ni++) {
                    float a0 = accA[mi][ni][0] + accB[mi][ni][0];
                    float a1 = accA[mi][ni][1] + accB[mi][ni][1];
                    float a2 = accA[mi][ni][2] + accB[mi][ni][2];
                    float a3 = accA[mi][ni][3] + accB[mi][ni][3];
                    int row = mi * 16 + erow, col = ecol + ni * 8;
                    writeA(sb, nbuf, row, col, tanh_f(a0), tanh_f(a1));
                    writeA(sb, nbuf, row + 8, col, tanh_f(a2), tanh_f(a3));
                }
        } else {                           // k_{s+1} = h@W2; RK update
            const bool fin = (s == 5);
            const float cc = c_cur[s];
            const float cb = c_b[s];
#pragma unroll
            for (int mi = 0; mi < 2; mi++)
#pragma unroll
                for (int ni = 0; ni < 2; ni++) {
                    const int idx = mi * 2 + ni;
                    const int fi = fbase + idx * 128;
                    float4 kc = make_float4(accA[mi][ni][0] + accB[mi][ni][0],
                                            accA[mi][ni][1] + accB[mi][ni][1],
                                            accA[mi][ni][2] + accB[mi][ni][2],
                                            accA[mi][ni][3] + accB[mi][ni][3]);
                    if (s <= 3) *(float4*)&g_k[s][fi] = kc;
                    float4 xv = xreg[idx];
                    if (s == 0) {
                        xacc[idx] = make_float4(fmaf(cb, kc.x, xv.x), fmaf(cb, kc.y, xv.y),
                                                fmaf(cb, kc.z, xv.z), fmaf(cb, kc.w, xv.w));
                    } else if (cb != 0.0f) {
                        float4 t = xacc[idx];
                        xacc[idx] = make_float4(fmaf(cb, kc.x, t.x), fmaf(cb, kc.y, t.y),
                                                fmaf(cb, kc.z, t.z), fmaf(cb, kc.w, t.w));
                    }
                    float4 na;
                    if (!fin) {            // y_{s+2} = x + cc*k_cur + sum_{sl<s} slots
                        na = make_float4(fmaf(cc, kc.x, xv.x), fmaf(cc, kc.y, xv.y),
                                         fmaf(cc, kc.z, xv.z), fmaf(cc, kc.w, xv.w));
                        // batched: all slot loads issue under predicates (sl < s)
                        float4 kv[4];
#pragma unroll
                        for (int sl = 0; sl < 4; sl++)
                            if (sl < s) kv[sl] = *(const float4*)&g_k[sl][fi];
#pragma unroll
                        for (int sl = 0; sl < 4; sl++)
                            if (sl < s) {
                                float cf = c_slot[s][sl];
                                na.x = fmaf(cf, kv[sl].x, na.x);
                                na.y = fmaf(cf, kv[sl].y, na.y);
                                na.z = fmaf(cf, kv[sl].z, na.z);
                                na.w = fmaf(cf, kv[sl].w, na.w);
                            }
                    } else {               // new x = xacc + h*b6*k6
                        float4 t = xacc[idx];
                        na = make_float4(fmaf(cc, kc.x, t.x), fmaf(cc, kc.y, t.y),
                                         fmaf(cc, kc.z, t.z), fmaf(cc, kc.w, t.w));
                        xreg[idx] = na;
                    }
                    int row = mi * 16 + erow, col = ecol + ni * 8;
                    if (g == NGEMM - 1) {
                        *(float2*)&out[(growb + row) * DIM + col] = make_float2(na.x, na.y);
                        *(float2*)&out[(growb + row + 8) * DIM + col] = make_float2(na.z, na.w);
                    } else {
                        writeA(sb, nbuf, row, col, na.x, na.y);
                        writeA(sb, nbuf, row + 8, col, na.z, na.w);
                    }
                }
        }
        __syncthreads();   // publish A buffer (g+1)&1
    }
}

extern "C" void kernel_launch(void* const* d_in, const int* in_sizes, int n_in,
                              void* d_out, int out_size) {
    (void)in_sizes; (void)n_in; (void)out_size;
    const float* x0 = (const float*)d_in[0];
    const float* W1 = (const float*)d_in[1];
    const float* W2 = (const float*)d_in[2];
    float* out = (float*)d_out;

    prep_kernel<<<256, 256>>>(W1, W2);
    cudaFuncSetAttribute(ode_hmma_kernel,
                         cudaFuncAttributeMaxDynamicSharedMemorySize, SMEM_BYTES);
    ode_hmma_kernel<<<NCTA, THREADS, SMEM_BYTES>>>(x0, out);
}